// round 9
// baseline (speedup 1.0000x reference)
#include <cuda_runtime.h>

#define IMG_W  512
#define IMG_H  512
#define IMG_N  (IMG_W * IMG_H)
#define TILE_X 64             /* output columns per CTA */
#define NT     32             /* ONE warp; each thread owns 2 adjacent columns */
#define TILE_Y 64
#define HALO   5
#define NITER  (TILE_Y + 2 * HALO)   /* 74 h-conv rows per tile */
#define ROW_E  76             /* smem row entries: cols x0-6 .. x0+69 */
#define MM_BLOCKS 1024
#define MM_THREADS 256

// Normalized 11-tap Gaussian, sigma=1.5, center at ws/2=5.5 (matches ref).
__device__ constexpr float GW[11] = {
    3.2030000e-04f, 2.9556500e-03f, 1.7487670e-02f, 6.6342420e-02f,
    1.6137299e-01f, 2.5168110e-01f, 2.5168110e-01f, 1.6137299e-01f,
    6.6342420e-02f, 1.7487670e-02f, 2.9556500e-03f
};

typedef unsigned long long u64;

__device__ __forceinline__ u64 pack2(float x, float y) {
    u64 r; asm("mov.b64 %0, {%1, %2};" : "=l"(r) : "f"(x), "f"(y)); return r;
}
__device__ __forceinline__ void unpack2(u64 v, float& x, float& y) {
    asm("mov.b64 {%0, %1}, %2;" : "=f"(x), "=f"(y) : "l"(v));
}
__device__ __forceinline__ u64 fma2(u64 a, u64 b, u64 c) {
    u64 d; asm("fma.rn.f32x2 %0, %1, %2, %3;" : "=l"(d) : "l"(a), "l"(b), "l"(c));
    return d;
}
__device__ __forceinline__ u64 mul2(u64 a, u64 b) {
    u64 d; asm("mul.rn.f32x2 %0, %1, %2;" : "=l"(d) : "l"(a), "l"(b));
    return d;
}

// ---------------------------------------------------------------------------
// Global min/max of img1 -> C1, C2 (single kernel, last-block finalize,
// self-resetting counter => graph-replay safe)
// ---------------------------------------------------------------------------
__device__ float g_blk_max[MM_BLOCKS];
__device__ float g_blk_min[MM_BLOCKS];
__device__ unsigned g_arrive = 0;
__device__ float g_C1, g_C2;

__global__ void __launch_bounds__(MM_THREADS)
minmax_kernel(const float4* __restrict__ x, int n4) {
    float mx = -3.402823466e38f, mn = 3.402823466e38f;
    const int stride = gridDim.x * blockDim.x;
    int i = blockIdx.x * blockDim.x + threadIdx.x;
#pragma unroll 8
    for (; i < n4; i += stride) {
        float4 v = x[i];
        mx = fmaxf(mx, fmaxf(fmaxf(v.x, v.y), fmaxf(v.z, v.w)));
        mn = fminf(mn, fminf(fminf(v.x, v.y), fminf(v.z, v.w)));
    }
#pragma unroll
    for (int o = 16; o > 0; o >>= 1) {
        mx = fmaxf(mx, __shfl_xor_sync(0xFFFFFFFFu, mx, o));
        mn = fminf(mn, __shfl_xor_sync(0xFFFFFFFFu, mn, o));
    }
    __shared__ float smx[8], smn[8];
    __shared__ bool last;
    const int w = threadIdx.x >> 5, l = threadIdx.x & 31;
    if (l == 0) { smx[w] = mx; smn[w] = mn; }
    __syncthreads();
    if (threadIdx.x == 0) {
#pragma unroll
        for (int k = 1; k < MM_THREADS / 32; ++k) {
            mx = fmaxf(mx, smx[k]); mn = fminf(mn, smn[k]);
        }
        g_blk_max[blockIdx.x] = mx;
        g_blk_min[blockIdx.x] = mn;
        __threadfence();
        last = (atomicAdd(&g_arrive, 1u) == (unsigned)(gridDim.x - 1));
    }
    __syncthreads();
    if (last) {
        float fx = -3.402823466e38f, fn = 3.402823466e38f;
#pragma unroll
        for (int k = 0; k < MM_BLOCKS / MM_THREADS; ++k) {
            fx = fmaxf(fx, g_blk_max[threadIdx.x + k * MM_THREADS]);
            fn = fminf(fn, g_blk_min[threadIdx.x + k * MM_THREADS]);
        }
#pragma unroll
        for (int o = 16; o > 0; o >>= 1) {
            fx = fmaxf(fx, __shfl_xor_sync(0xFFFFFFFFu, fx, o));
            fn = fminf(fn, __shfl_xor_sync(0xFFFFFFFFu, fn, o));
        }
        if (l == 0) { smx[w] = fx; smn[w] = fn; }
        __syncthreads();
        if (threadIdx.x == 0) {
#pragma unroll
            for (int k = 1; k < MM_THREADS / 32; ++k) {
                fx = fmaxf(fx, smx[k]); fn = fminf(fn, smn[k]);
            }
            float L = fx - fn;
            if (L == 0.f) L = 5.f;
            g_C1 = (0.01f * L) * (0.01f * L);
            g_C2 = (0.03f * L) * (0.03f * L);
            g_arrive = 0;
        }
    }
}

// ---------------------------------------------------------------------------
// Fused separable-SSIM: single-warp CTAs, 2 px/thread, fully packed f32x2
// datapath (values, squares, and cross-pixel-packed ab all precomputed in
// smem; v-pass s12 ring packed across the pixel pair)
// ---------------------------------------------------------------------------
struct RowLd { float2 i1, i2, h1, h2; };

__device__ __forceinline__ RowLd load_row(const float* __restrict__ p1,
                                          const float* __restrict__ p2,
                                          int hy, int x0, int tx) {
    RowLd r;
    r.i1 = make_float2(0.f, 0.f); r.i2 = r.i1; r.h1 = r.i1; r.h2 = r.i1;
    if ((unsigned)hy < (unsigned)IMG_H) {
        const int base = hy * IMG_W;
        const int cI = x0 - 6 + 2 * tx;              // even -> aligned float2
        if ((unsigned)cI < (unsigned)IMG_W) {
            r.i1 = *(const float2*)(p1 + base + cI);
            r.i2 = *(const float2*)(p2 + base + cI);
        }
        if (tx < 6) {
            const int cH = cI + TILE_X;              // j = 64 + 2tx
            if ((unsigned)cH < (unsigned)IMG_W) {
                r.h1 = *(const float2*)(p1 + base + cH);
                r.h2 = *(const float2*)(p2 + base + cH);
            }
        }
    }
    return r;
}

__global__ void __launch_bounds__(NT)
ssim_kernel(const float* __restrict__ img1, const float* __restrict__ img2,
            float* __restrict__ out) {
    const int tx = threadIdx.x;
    const int x0 = blockIdx.x * TILE_X;
    const int y0 = blockIdx.y * TILE_Y;
    const long imgoff = (long)blockIdx.z * IMG_N;
    const float* p1 = img1 + imgoff;
    const float* p2 = img2 + imgoff;
    float* po = out + imgoff;

    const float C1 = g_C1;
    const float C2 = g_C2;

    // two alternating buffer-sets, each a PAIR of rows.
    // entry j <-> image col x0-6+j, j = 0..75
    __shared__ u64 spab[2][2][ROW_E];   // (v1[j],  v2[j])   packed
    __shared__ u64 spp [2][2][ROW_E];   // (v1²[j], v2²[j])  packed
    __shared__ u64 sabp[2][2][ROW_E];   // (ab[j],  ab[j+1]) packed (overlap)

    u64 WW6[6];
#pragma unroll
    for (int k = 0; k < 6; ++k) WW6[k] = pack2(GW[k], GW[k]);

    // per-pixel vertical rings; s12 ring packed across the pixel pair
    u64 rm12[2][11], r1122[2][11], r12p[11];
#pragma unroll
    for (int k = 0; k < 11; ++k) {
        rm12[0][k] = 0ull; rm12[1][k] = 0ull;
        r1122[0][k] = 0ull; r1122[1][k] = 0ull;
        r12p[k] = 0ull;
    }

    RowLd R0 = load_row(p1, p2, y0 - HALO,     x0, tx);
    RowLd R1 = load_row(p1, p2, y0 - HALO + 1, x0, tx);
    int bs = 0;

    // Publish one row: values, squares, cross-packed ab pairs.
    // abp[j] = (ab[j], ab[j+1]); thread owns j = 2tx, 2tx+1 (+halo for tx<6).
#define PUBLISH(RR, RL)                                                        \
    do {                                                                       \
        const u64 q0 = pack2((RL).i1.x, (RL).i2.x);                            \
        const u64 q1 = pack2((RL).i1.y, (RL).i2.y);                            \
        const float e0 = (RL).i1.x * (RL).i2.x;                                \
        const float e1 = (RL).i1.y * (RL).i2.y;                                \
        const float f0 = (RL).h1.x * (RL).h2.x;                                \
        const float f1 = (RL).h1.y * (RL).h2.y;                                \
        float n0 = __shfl_down_sync(0xFFFFFFFFu, e0, 1);                       \
        const float f0_l0 = __shfl_sync(0xFFFFFFFFu, f0, 0);                   \
        const float nf0   = __shfl_down_sync(0xFFFFFFFFu, f0, 1);              \
        if (tx == 31) n0 = f0_l0;                                              \
        spab[bs][RR][2 * tx]     = q0;                                         \
        spab[bs][RR][2 * tx + 1] = q1;                                         \
        spp [bs][RR][2 * tx]     = mul2(q0, q0);                               \
        spp [bs][RR][2 * tx + 1] = mul2(q1, q1);                               \
        sabp[bs][RR][2 * tx]     = pack2(e0, e1);                              \
        sabp[bs][RR][2 * tx + 1] = pack2(e1, n0);                              \
        if (tx < 6) {                                                          \
            const u64 qh0 = pack2((RL).h1.x, (RL).h2.x);                       \
            const u64 qh1 = pack2((RL).h1.y, (RL).h2.y);                       \
            spab[bs][RR][TILE_X + 2 * tx]     = qh0;                           \
            spab[bs][RR][TILE_X + 2 * tx + 1] = qh1;                           \
            spp [bs][RR][TILE_X + 2 * tx]     = mul2(qh0, qh0);                \
            spp [bs][RR][TILE_X + 2 * tx + 1] = mul2(qh1, qh1);                \
            sabp[bs][RR][TILE_X + 2 * tx]     = pack2(f0, f1);                 \
            sabp[bs][RR][TILE_X + 2 * tx + 1] = pack2(f1, tx < 5 ? nf0 : 0.f); \
        }                                                                      \
    } while (0)

    // h-pass for BOTH pixels: 5 fma2 + 3 LDS.64 per tap (rolling p/pp temps).
    // px A taps at j = jb+k, px B at jb+k+1 (jb = 2tx+1).
#define HPASS2(SLOT, RR)                                                       \
    do {                                                                       \
        const int jb = 2 * tx + 1;                                             \
        u64 hA01 = 0ull, hA23 = 0ull, hB01 = 0ull, hB23 = 0ull, hAB = 0ull;    \
        u64 pP  = spab[bs][RR][jb];                                            \
        u64 ppP = spp [bs][RR][jb];                                            \
        _Pragma("unroll")                                                      \
        for (int k = 0; k < 11; ++k) {                                         \
            const int kk = (k <= 5) ? k : (11 - k);                            \
            const u64 pC  = spab[bs][RR][jb + k + 1];                          \
            const u64 ppC = spp [bs][RR][jb + k + 1];                          \
            const u64 abC = sabp[bs][RR][jb + k];                              \
            hA01 = fma2(pP,  WW6[kk], hA01);                                   \
            hA23 = fma2(ppP, WW6[kk], hA23);                                   \
            hB01 = fma2(pC,  WW6[kk], hB01);                                   \
            hB23 = fma2(ppC, WW6[kk], hB23);                                   \
            hAB  = fma2(abC, WW6[kk], hAB);                                    \
            pP = pC; ppP = ppC;                                                \
        }                                                                      \
        rm12[0][SLOT] = hA01; r1122[0][SLOT] = hA23;                           \
        rm12[1][SLOT] = hB01; r1122[1][SLOT] = hB23;                           \
        r12p[SLOT] = hAB;                                                      \
    } while (0)

    // merged v-pass for both pixels: 5 fma2 per tap
#define VPASS2(SLOT, ROW)                                                      \
    do {                                                                       \
        u64 MA = 0ull, SA = 0ull, MB = 0ull, SB = 0ull, S12 = 0ull;            \
        _Pragma("unroll")                                                      \
        for (int k = 0; k < 11; ++k) {                                         \
            const int s  = ((SLOT) + 1 + k) % 11;                              \
            const int kk = (k <= 5) ? k : (11 - k);                            \
            MA  = fma2(rm12[0][s],  WW6[kk], MA);                              \
            SA  = fma2(r1122[0][s], WW6[kk], SA);                              \
            MB  = fma2(rm12[1][s],  WW6[kk], MB);                              \
            SB  = fma2(r1122[1][s], WW6[kk], SB);                              \
            S12 = fma2(r12p[s],     WW6[kk], S12);                             \
        }                                                                      \
        float s12A, s12B;                                                      \
        unpack2(S12, s12A, s12B);                                              \
        float2 res;                                                            \
        {                                                                      \
            float mu1, mu2, e11, e22;                                          \
            unpack2(MA, mu1, mu2); unpack2(SA, e11, e22);                      \
            const float mu1sq = mu1 * mu1;                                     \
            const float mu2sq = mu2 * mu2;                                     \
            const float mu12  = mu1 * mu2;                                     \
            const float num = fmaf(2.f, mu12, C1) *                            \
                              fmaf(2.f, s12A - mu12, C2);                      \
            const float den = (mu1sq + mu2sq + C1) *                           \
                              ((e11 - mu1sq) + (e22 - mu2sq) + C2);            \
            res.x = __fdividef(num, den);                                      \
        }                                                                      \
        {                                                                      \
            float mu1, mu2, e11, e22;                                          \
            unpack2(MB, mu1, mu2); unpack2(SB, e11, e22);                      \
            const float mu1sq = mu1 * mu1;                                     \
            const float mu2sq = mu2 * mu2;                                     \
            const float mu12  = mu1 * mu2;                                     \
            const float num = fmaf(2.f, mu12, C1) *                            \
                              fmaf(2.f, s12B - mu12, C2);                      \
            const float den = (mu1sq + mu2sq + C1) *                           \
                              ((e11 - mu1sq) + (e22 - mu2sq) + C2);            \
            res.y = __fdividef(num, den);                                      \
        }                                                                      \
        *(float2*)(po + (y0 + (ROW) - 2 * HALO) * IMG_W + x0 + 2 * tx) = res;  \
    } while (0)

    for (int ib = 0; ib < NITER; ib += 22) {
#pragma unroll
        for (int jj = 0; jj < 11; ++jj) {
            const int i0 = ib + 2 * jj;
            if (i0 < NITER) {
                PUBLISH(0, R0);
                PUBLISH(1, R1);
                // prefetch next pair (consumed after next sync)
                R0 = load_row(p1, p2, y0 - HALO + i0 + 2, x0, tx);
                R1 = load_row(p1, p2, y0 - HALO + i0 + 3, x0, tx);
                __syncwarp();    // publish -> consume handshake

                const int s0 = (2 * jj) % 11;       // compile-time
                const int s1 = (2 * jj + 1) % 11;   // compile-time
                HPASS2(s0, 0);
                if (i0 >= 2 * HALO) VPASS2(s0, i0);
                HPASS2(s1, 1);
                if (i0 >= 2 * HALO) VPASS2(s1, i0 + 1);
                bs ^= 1;
                // republish of this buffer set is ordered behind the NEXT
                // iteration's __syncwarp -> one sync per iteration suffices
            }
        }
    }
#undef PUBLISH
#undef HPASS2
#undef VPASS2
}

// ---------------------------------------------------------------------------
extern "C" void kernel_launch(void* const* d_in, const int* in_sizes, int n_in,
                              void* d_out, int out_size) {
    const float* img1 = (const float*)d_in[0];
    const float* img2 = (const float*)d_in[1];
    float* out = (float*)d_out;
    const int n = in_sizes[0];                 // 32*1*512*512 = 8388608

    minmax_kernel<<<MM_BLOCKS, MM_THREADS>>>((const float4*)img1, n / 4);

    dim3 grid(IMG_W / TILE_X, IMG_H / TILE_Y, n / IMG_N);   // (8, 8, 32)
    ssim_kernel<<<grid, NT>>>(img1, img2, out);
}

// round 10
// speedup vs baseline: 1.1444x; 1.1444x over previous
#include <cuda_runtime.h>

#define IMG_W  512
#define IMG_H  512
#define IMG_N  (IMG_W * IMG_H)
#define TILE_X 128            /* output columns per CTA */
#define NT     64             /* 2 warps; each thread owns 2 adjacent columns */
#define TILE_Y 64
#define HALO   5
#define NITER  (TILE_Y + 2 * HALO)   /* 74 h-conv rows per tile */
#define ROW_E  140            /* smem row entries: cols x0-6 .. x0+133 */
#define MM_BLOCKS 1024
#define MM_THREADS 256

// Normalized 11-tap Gaussian, sigma=1.5, center at ws/2=5.5 (matches ref).
__device__ constexpr float GW[11] = {
    3.2030000e-04f, 2.9556500e-03f, 1.7487670e-02f, 6.6342420e-02f,
    1.6137299e-01f, 2.5168110e-01f, 2.5168110e-01f, 1.6137299e-01f,
    6.6342420e-02f, 1.7487670e-02f, 2.9556500e-03f
};

typedef unsigned long long u64;

__device__ __forceinline__ u64 pack2(float x, float y) {
    u64 r; asm("mov.b64 %0, {%1, %2};" : "=l"(r) : "f"(x), "f"(y)); return r;
}
__device__ __forceinline__ void unpack2(u64 v, float& x, float& y) {
    asm("mov.b64 {%0, %1}, %2;" : "=f"(x), "=f"(y) : "l"(v));
}
__device__ __forceinline__ u64 fma2(u64 a, u64 b, u64 c) {
    u64 d; asm("fma.rn.f32x2 %0, %1, %2, %3;" : "=l"(d) : "l"(a), "l"(b), "l"(c));
    return d;
}
__device__ __forceinline__ u64 mul2(u64 a, u64 b) {
    u64 d; asm("mul.rn.f32x2 %0, %1, %2;" : "=l"(d) : "l"(a), "l"(b));
    return d;
}

// ---------------------------------------------------------------------------
// Global min/max of img1 -> C1, C2 (single kernel, last-block finalize,
// self-resetting counter => graph-replay safe)
// ---------------------------------------------------------------------------
__device__ float g_blk_max[MM_BLOCKS];
__device__ float g_blk_min[MM_BLOCKS];
__device__ unsigned g_arrive = 0;
__device__ float g_C1, g_C2;

__global__ void __launch_bounds__(MM_THREADS)
minmax_kernel(const float4* __restrict__ x, int n4) {
    float mx = -3.402823466e38f, mn = 3.402823466e38f;
    const int stride = gridDim.x * blockDim.x;
    int i = blockIdx.x * blockDim.x + threadIdx.x;
#pragma unroll 8
    for (; i < n4; i += stride) {
        float4 v = x[i];
        mx = fmaxf(mx, fmaxf(fmaxf(v.x, v.y), fmaxf(v.z, v.w)));
        mn = fminf(mn, fminf(fminf(v.x, v.y), fminf(v.z, v.w)));
    }
#pragma unroll
    for (int o = 16; o > 0; o >>= 1) {
        mx = fmaxf(mx, __shfl_xor_sync(0xFFFFFFFFu, mx, o));
        mn = fminf(mn, __shfl_xor_sync(0xFFFFFFFFu, mn, o));
    }
    __shared__ float smx[8], smn[8];
    __shared__ bool last;
    const int w = threadIdx.x >> 5, l = threadIdx.x & 31;
    if (l == 0) { smx[w] = mx; smn[w] = mn; }
    __syncthreads();
    if (threadIdx.x == 0) {
#pragma unroll
        for (int k = 1; k < MM_THREADS / 32; ++k) {
            mx = fmaxf(mx, smx[k]); mn = fminf(mn, smn[k]);
        }
        g_blk_max[blockIdx.x] = mx;
        g_blk_min[blockIdx.x] = mn;
        __threadfence();
        last = (atomicAdd(&g_arrive, 1u) == (unsigned)(gridDim.x - 1));
    }
    __syncthreads();
    if (last) {
        float fx = -3.402823466e38f, fn = 3.402823466e38f;
#pragma unroll
        for (int k = 0; k < MM_BLOCKS / MM_THREADS; ++k) {
            fx = fmaxf(fx, g_blk_max[threadIdx.x + k * MM_THREADS]);
            fn = fminf(fn, g_blk_min[threadIdx.x + k * MM_THREADS]);
        }
#pragma unroll
        for (int o = 16; o > 0; o >>= 1) {
            fx = fmaxf(fx, __shfl_xor_sync(0xFFFFFFFFu, fx, o));
            fn = fminf(fn, __shfl_xor_sync(0xFFFFFFFFu, fn, o));
        }
        if (l == 0) { smx[w] = fx; smn[w] = fn; }
        __syncthreads();
        if (threadIdx.x == 0) {
#pragma unroll
            for (int k = 1; k < MM_THREADS / 32; ++k) {
                fx = fmaxf(fx, smx[k]); fn = fminf(fn, smn[k]);
            }
            float L = fx - fn;
            if (L == 0.f) L = 5.f;
            g_C1 = (0.01f * L) * (0.01f * L);
            g_C2 = (0.03f * L) * (0.03f * L);
            g_arrive = 0;
        }
    }
}

// ---------------------------------------------------------------------------
// Fused separable-SSIM: 2-warp CTAs, 128-wide tile (low halo), 2 px/thread,
// rolling tap temps, packed f32x2 datapath, s12 v-ring packed across the
// pixel pair, ONE barrier per row-pair iteration
// ---------------------------------------------------------------------------
struct RowLd { float2 i1, i2, h1, h2; };

__device__ __forceinline__ RowLd load_row(const float* __restrict__ p1,
                                          const float* __restrict__ p2,
                                          int hy, int x0, int tx) {
    RowLd r;
    r.i1 = make_float2(0.f, 0.f); r.i2 = r.i1; r.h1 = r.i1; r.h2 = r.i1;
    if ((unsigned)hy < (unsigned)IMG_H) {
        const int base = hy * IMG_W;
        const int cI = x0 - 6 + 2 * tx;              // even -> aligned float2
        if ((unsigned)cI < (unsigned)IMG_W) {
            r.i1 = *(const float2*)(p1 + base + cI);
            r.i2 = *(const float2*)(p2 + base + cI);
        }
        if (tx < 6) {
            const int cH = cI + TILE_X;              // j = 128 + 2tx
            if ((unsigned)cH < (unsigned)IMG_W) {
                r.h1 = *(const float2*)(p1 + base + cH);
                r.h2 = *(const float2*)(p2 + base + cH);
            }
        }
    }
    return r;
}

__global__ void __launch_bounds__(NT, 7)
ssim_kernel(const float* __restrict__ img1, const float* __restrict__ img2,
            float* __restrict__ out) {
    const int tx = threadIdx.x;
    const int x0 = blockIdx.x * TILE_X;
    const int y0 = blockIdx.y * TILE_Y;
    const long imgoff = (long)blockIdx.z * IMG_N;
    const float* p1 = img1 + imgoff;
    const float* p2 = img2 + imgoff;
    float* po = out + imgoff;

    const float C1 = g_C1;
    const float C2 = g_C2;

    // two alternating buffer-sets, each a PAIR of rows.
    // entry j <-> image col x0-6+j, j = 0..139
    __shared__ u64   spab[2][2][ROW_E];   // (img1, img2) packed per column
    __shared__ float sab [2][2][ROW_E];   // img1*img2 per column

    u64 WW6[6];
#pragma unroll
    for (int k = 0; k < 6; ++k) WW6[k] = pack2(GW[k], GW[k]);

    // per-pixel vertical rings; s12 ring packed across the pixel pair
    u64 rm12[2][11], r1122[2][11], r12p[11];
#pragma unroll
    for (int k = 0; k < 11; ++k) {
        rm12[0][k] = 0ull; rm12[1][k] = 0ull;
        r1122[0][k] = 0ull; r1122[1][k] = 0ull;
        r12p[k] = 0ull;
    }

    RowLd R0 = load_row(p1, p2, y0 - HALO,     x0, tx);
    RowLd R1 = load_row(p1, p2, y0 - HALO + 1, x0, tx);
    int bs = 0;

#define PUBLISH(RR, RL)                                                        \
    do {                                                                       \
        ulonglong2 q;                                                          \
        q.x = pack2((RL).i1.x, (RL).i2.x);                                     \
        q.y = pack2((RL).i1.y, (RL).i2.y);                                     \
        *(ulonglong2*)&spab[bs][RR][2 * tx] = q;                               \
        *(float2*)&sab[bs][RR][2 * tx] =                                       \
            make_float2((RL).i1.x * (RL).i2.x, (RL).i1.y * (RL).i2.y);         \
        if (tx < 6) {                                                          \
            ulonglong2 qh;                                                     \
            qh.x = pack2((RL).h1.x, (RL).h2.x);                                \
            qh.y = pack2((RL).h1.y, (RL).h2.y);                                \
            *(ulonglong2*)&spab[bs][RR][TILE_X + 2 * tx] = qh;                 \
            *(float2*)&sab[bs][RR][TILE_X + 2 * tx] =                          \
                make_float2((RL).h1.x * (RL).h2.x, (RL).h1.y * (RL).h2.y);     \
        }                                                                      \
    } while (0)

    // h-pass for BOTH pixels, rolling 2-deep tap window (low live regs).
    // taps: px A at j = jb+k, px B at jb+k+1 (jb = 2tx+1).
#define HPASS2(SLOT, RR)                                                       \
    do {                                                                       \
        const int jb = 2 * tx + 1;                                             \
        u64 hA01 = 0ull, hA23 = 0ull, hB01 = 0ull, hB23 = 0ull;                \
        float hA4 = 0.f, hB4 = 0.f;                                            \
        u64   pP  = spab[bs][RR][jb];                                          \
        u64   ppP = mul2(pP, pP);                                              \
        float abP = sab[bs][RR][jb];                                           \
        _Pragma("unroll")                                                      \
        for (int k = 0; k < 11; ++k) {                                         \
            const int kk = (k <= 5) ? k : (11 - k);                            \
            const u64   pC  = spab[bs][RR][jb + k + 1];                        \
            const u64   ppC = mul2(pC, pC);                                    \
            const float abC = sab[bs][RR][jb + k + 1];                         \
            hA01 = fma2(pP,  WW6[kk], hA01);                                   \
            hA23 = fma2(ppP, WW6[kk], hA23);                                   \
            hA4  = fmaf(abP, GW[k],   hA4);                                    \
            hB01 = fma2(pC,  WW6[kk], hB01);                                   \
            hB23 = fma2(ppC, WW6[kk], hB23);                                   \
            hB4  = fmaf(abC, GW[k],   hB4);                                    \
            pP = pC; ppP = ppC; abP = abC;                                     \
        }                                                                      \
        rm12[0][SLOT] = hA01; r1122[0][SLOT] = hA23;                           \
        rm12[1][SLOT] = hB01; r1122[1][SLOT] = hB23;                           \
        r12p[SLOT] = pack2(hA4, hB4);                                          \
    } while (0)

    // merged v-pass for both pixels: 5 fma2 per tap
#define VPASS2(SLOT, ROW)                                                      \
    do {                                                                       \
        u64 MA = 0ull, SA = 0ull, MB = 0ull, SB = 0ull, S12 = 0ull;            \
        _Pragma("unroll")                                                      \
        for (int k = 0; k < 11; ++k) {                                         \
            const int s  = ((SLOT) + 1 + k) % 11;                              \
            const int kk = (k <= 5) ? k : (11 - k);                            \
            MA  = fma2(rm12[0][s],  WW6[kk], MA);                              \
            SA  = fma2(r1122[0][s], WW6[kk], SA);                              \
            MB  = fma2(rm12[1][s],  WW6[kk], MB);                              \
            SB  = fma2(r1122[1][s], WW6[kk], SB);                              \
            S12 = fma2(r12p[s],     WW6[kk], S12);                             \
        }                                                                      \
        float s12A, s12B;                                                      \
        unpack2(S12, s12A, s12B);                                              \
        float2 res;                                                            \
        {                                                                      \
            float mu1, mu2, e11, e22;                                          \
            unpack2(MA, mu1, mu2); unpack2(SA, e11, e22);                      \
            const float mu1sq = mu1 * mu1;                                     \
            const float mu2sq = mu2 * mu2;                                     \
            const float mu12  = mu1 * mu2;                                     \
            const float num = fmaf(2.f, mu12, C1) *                            \
                              fmaf(2.f, s12A - mu12, C2);                      \
            const float den = (mu1sq + mu2sq + C1) *                           \
                              ((e11 - mu1sq) + (e22 - mu2sq) + C2);            \
            res.x = __fdividef(num, den);                                      \
        }                                                                      \
        {                                                                      \
            float mu1, mu2, e11, e22;                                          \
            unpack2(MB, mu1, mu2); unpack2(SB, e11, e22);                      \
            const float mu1sq = mu1 * mu1;                                     \
            const float mu2sq = mu2 * mu2;                                     \
            const float mu12  = mu1 * mu2;                                     \
            const float num = fmaf(2.f, mu12, C1) *                            \
                              fmaf(2.f, s12B - mu12, C2);                      \
            const float den = (mu1sq + mu2sq + C1) *                           \
                              ((e11 - mu1sq) + (e22 - mu2sq) + C2);            \
            res.y = __fdividef(num, den);                                      \
        }                                                                      \
        *(float2*)(po + (y0 + (ROW) - 2 * HALO) * IMG_W + x0 + 2 * tx) = res;  \
    } while (0)

    for (int ib = 0; ib < NITER; ib += 22) {
#pragma unroll
        for (int jj = 0; jj < 11; ++jj) {
            const int i0 = ib + 2 * jj;
            if (i0 < NITER) {
                PUBLISH(0, R0);
                PUBLISH(1, R1);
                // prefetch next pair (consumed after next barrier)
                R0 = load_row(p1, p2, y0 - HALO + i0 + 2, x0, tx);
                R1 = load_row(p1, p2, y0 - HALO + i0 + 3, x0, tx);
                __syncthreads();

                const int s0 = (2 * jj) % 11;       // compile-time
                const int s1 = (2 * jj + 1) % 11;   // compile-time
                HPASS2(s0, 0);
                if (i0 >= 2 * HALO) VPASS2(s0, i0);
                HPASS2(s1, 1);
                if (i0 >= 2 * HALO) VPASS2(s1, i0 + 1);
                bs ^= 1;
                // republish of this buffer set happens only after the NEXT
                // iteration's barrier -> one barrier per iteration suffices
            }
        }
    }
#undef PUBLISH
#undef HPASS2
#undef VPASS2
}

// ---------------------------------------------------------------------------
extern "C" void kernel_launch(void* const* d_in, const int* in_sizes, int n_in,
                              void* d_out, int out_size) {
    const float* img1 = (const float*)d_in[0];
    const float* img2 = (const float*)d_in[1];
    float* out = (float*)d_out;
    const int n = in_sizes[0];                 // 32*1*512*512 = 8388608

    minmax_kernel<<<MM_BLOCKS, MM_THREADS>>>((const float4*)img1, n / 4);

    dim3 grid(IMG_W / TILE_X, IMG_H / TILE_Y, n / IMG_N);   // (4, 8, 32)
    ssim_kernel<<<grid, NT>>>(img1, img2, out);
}

// round 13
// speedup vs baseline: 1.3431x; 1.1737x over previous
#include <cuda_runtime.h>

#define IMG_W  512
#define IMG_H  512
#define IMG_N  (IMG_W * IMG_H)
#define TILE_X 64             /* output columns per CTA */
#define NT     32             /* ONE warp; each thread owns 2 adjacent columns */
#define TILE_Y 64
#define HALO   5
#define NITER  (TILE_Y + 2 * HALO)   /* 74 h-conv rows per tile */
#define ROW_E  76             /* smem row entries: cols x0-6 .. x0+69 */
#define MM_BLOCKS 1024
#define MM_THREADS 256

// Normalized 11-tap Gaussian, sigma=1.5, center at ws/2=5.5 (matches ref).
__device__ constexpr float GW[11] = {
    3.2030000e-04f, 2.9556500e-03f, 1.7487670e-02f, 6.6342420e-02f,
    1.6137299e-01f, 2.5168110e-01f, 2.5168110e-01f, 1.6137299e-01f,
    6.6342420e-02f, 1.7487670e-02f, 2.9556500e-03f
};

typedef unsigned long long u64;

__device__ __forceinline__ u64 pack2(float x, float y) {
    u64 r; asm("mov.b64 %0, {%1, %2};" : "=l"(r) : "f"(x), "f"(y)); return r;
}
__device__ __forceinline__ void unpack2(u64 v, float& x, float& y) {
    asm("mov.b64 {%0, %1}, %2;" : "=f"(x), "=f"(y) : "l"(v));
}
__device__ __forceinline__ u64 fma2(u64 a, u64 b, u64 c) {
    u64 d; asm("fma.rn.f32x2 %0, %1, %2, %3;" : "=l"(d) : "l"(a), "l"(b), "l"(c));
    return d;
}
__device__ __forceinline__ u64 mul2(u64 a, u64 b) {
    u64 d; asm("mul.rn.f32x2 %0, %1, %2;" : "=l"(d) : "l"(a), "l"(b));
    return d;
}

// ---------------------------------------------------------------------------
// Global min/max of img1 -> C1, C2 (single kernel, last-block finalize,
// self-resetting counter => graph-replay safe)
// ---------------------------------------------------------------------------
__device__ float g_blk_max[MM_BLOCKS];
__device__ float g_blk_min[MM_BLOCKS];
__device__ unsigned g_arrive = 0;
__device__ float g_C1, g_C2;

__global__ void __launch_bounds__(MM_THREADS)
minmax_kernel(const float4* __restrict__ x, int n4) {
    float mx = -3.402823466e38f, mn = 3.402823466e38f;
    const int stride = gridDim.x * blockDim.x;
    int i = blockIdx.x * blockDim.x + threadIdx.x;
#pragma unroll 8
    for (; i < n4; i += stride) {
        float4 v = x[i];
        mx = fmaxf(mx, fmaxf(fmaxf(v.x, v.y), fmaxf(v.z, v.w)));
        mn = fminf(mn, fminf(fminf(v.x, v.y), fminf(v.z, v.w)));
    }
#pragma unroll
    for (int o = 16; o > 0; o >>= 1) {
        mx = fmaxf(mx, __shfl_xor_sync(0xFFFFFFFFu, mx, o));
        mn = fminf(mn, __shfl_xor_sync(0xFFFFFFFFu, mn, o));
    }
    __shared__ float smx[8], smn[8];
    __shared__ bool last;
    const int w = threadIdx.x >> 5, l = threadIdx.x & 31;
    if (l == 0) { smx[w] = mx; smn[w] = mn; }
    __syncthreads();
    if (threadIdx.x == 0) {
#pragma unroll
        for (int k = 1; k < MM_THREADS / 32; ++k) {
            mx = fmaxf(mx, smx[k]); mn = fminf(mn, smn[k]);
        }
        g_blk_max[blockIdx.x] = mx;
        g_blk_min[blockIdx.x] = mn;
        __threadfence();
        last = (atomicAdd(&g_arrive, 1u) == (unsigned)(gridDim.x - 1));
    }
    __syncthreads();
    if (last) {
        float fx = -3.402823466e38f, fn = 3.402823466e38f;
#pragma unroll
        for (int k = 0; k < MM_BLOCKS / MM_THREADS; ++k) {
            fx = fmaxf(fx, g_blk_max[threadIdx.x + k * MM_THREADS]);
            fn = fminf(fn, g_blk_min[threadIdx.x + k * MM_THREADS]);
        }
#pragma unroll
        for (int o = 16; o > 0; o >>= 1) {
            fx = fmaxf(fx, __shfl_xor_sync(0xFFFFFFFFu, fx, o));
            fn = fminf(fn, __shfl_xor_sync(0xFFFFFFFFu, fn, o));
        }
        if (l == 0) { smx[w] = fx; smn[w] = fn; }
        __syncthreads();
        if (threadIdx.x == 0) {
#pragma unroll
            for (int k = 1; k < MM_THREADS / 32; ++k) {
                fx = fmaxf(fx, smx[k]); fn = fminf(fn, smn[k]);
            }
            float L = fx - fn;
            if (L == 0.f) L = 5.f;
            g_C1 = (0.01f * L) * (0.01f * L);
            g_C2 = (0.03f * L) * (0.03f * L);
            g_arrive = 0;
        }
    }
}

// ---------------------------------------------------------------------------
// Fused separable-SSIM, 4-channel formulation:
//   convolve (a,b) and (p,q) = ((a+b)^2, (a-b)^2); then
//   sigma1+sigma2 = (Ep+Eq)/2 - mu1^2 - mu2^2,  sigma12 = (Ep-Eq)/4 - mu1*mu2.
// Single-warp CTAs, 2 px/thread, rolling tap temps, one syncwarp/iteration.
// ---------------------------------------------------------------------------
struct RowLd { float2 i1, i2, h1, h2; };

__device__ __forceinline__ RowLd load_row(const float* __restrict__ p1,
                                          const float* __restrict__ p2,
                                          int hy, int x0, int tx) {
    RowLd r;
    r.i1 = make_float2(0.f, 0.f); r.i2 = r.i1; r.h1 = r.i1; r.h2 = r.i1;
    if ((unsigned)hy < (unsigned)IMG_H) {
        const int base = hy * IMG_W;
        const int cI = x0 - 6 + 2 * tx;              // even -> aligned float2
        if ((unsigned)cI < (unsigned)IMG_W) {
            r.i1 = *(const float2*)(p1 + base + cI);
            r.i2 = *(const float2*)(p2 + base + cI);
        }
        if (tx < 6) {
            const int cH = cI + TILE_X;              // j = 64 + 2tx
            if ((unsigned)cH < (unsigned)IMG_W) {
                r.h1 = *(const float2*)(p1 + base + cH);
                r.h2 = *(const float2*)(p2 + base + cH);
            }
        }
    }
    return r;
}

__global__ void __launch_bounds__(NT)
ssim_kernel(const float* __restrict__ img1, const float* __restrict__ img2,
            float* __restrict__ out) {
    const int tx = threadIdx.x;
    const int x0 = blockIdx.x * TILE_X;
    const int y0 = blockIdx.y * TILE_Y;
    const long imgoff = (long)blockIdx.z * IMG_N;
    const float* p1 = img1 + imgoff;
    const float* p2 = img2 + imgoff;
    float* po = out + imgoff;

    const float C1 = g_C1;
    const float C2 = g_C2;

    // two alternating buffer-sets, each a PAIR of rows.
    // entry j <-> image col x0-6+j, j = 0..75
    __shared__ u64 spab[2][2][ROW_E];   // (a, b) packed per column
    __shared__ u64 spq [2][2][ROW_E];   // ((a+b)^2, (a-b)^2) packed per column

    u64 WW6[6];
#pragma unroll
    for (int k = 0; k < 6; ++k) WW6[k] = pack2(GW[k], GW[k]);

    // per-pixel vertical rings: packed (mu1,mu2) and packed (Ep,Eq)
    u64 rm[2][11], rq[2][11];
#pragma unroll
    for (int k = 0; k < 11; ++k) {
        rm[0][k] = 0ull; rm[1][k] = 0ull;
        rq[0][k] = 0ull; rq[1][k] = 0ull;
    }

    RowLd R0 = load_row(p1, p2, y0 - HALO,     x0, tx);
    RowLd R1 = load_row(p1, p2, y0 - HALO + 1, x0, tx);
    int bs = 0;

    // Publish one row: (a,b) pairs and ((a+b)^2,(a-b)^2) pairs.
#define PUBLISH(RR, RL)                                                        \
    do {                                                                       \
        ulonglong2 v, s;                                                       \
        v.x = pack2((RL).i1.x, (RL).i2.x);                                     \
        v.y = pack2((RL).i1.y, (RL).i2.y);                                     \
        const u64 sd0 = pack2((RL).i1.x + (RL).i2.x, (RL).i1.x - (RL).i2.x);   \
        const u64 sd1 = pack2((RL).i1.y + (RL).i2.y, (RL).i1.y - (RL).i2.y);   \
        s.x = mul2(sd0, sd0);                                                  \
        s.y = mul2(sd1, sd1);                                                  \
        *(ulonglong2*)&spab[bs][RR][2 * tx] = v;                               \
        *(ulonglong2*)&spq [bs][RR][2 * tx] = s;                               \
        if (tx < 6) {                                                          \
            ulonglong2 vh, sh;                                                 \
            vh.x = pack2((RL).h1.x, (RL).h2.x);                                \
            vh.y = pack2((RL).h1.y, (RL).h2.y);                                \
            const u64 hd0 = pack2((RL).h1.x + (RL).h2.x,                       \
                                  (RL).h1.x - (RL).h2.x);                      \
            const u64 hd1 = pack2((RL).h1.y + (RL).h2.y,                       \
                                  (RL).h1.y - (RL).h2.y);                      \
            sh.x = mul2(hd0, hd0);                                             \
            sh.y = mul2(hd1, hd1);                                             \
            *(ulonglong2*)&spab[bs][RR][TILE_X + 2 * tx] = vh;                 \
            *(ulonglong2*)&spq [bs][RR][TILE_X + 2 * tx] = sh;                 \
        }                                                                      \
    } while (0)

    // h-pass for BOTH pixels: per tap 2 LDS.64 + 4 fma2, rolling temps.
    // px A taps at j = jb+k, px B at jb+k+1 (jb = 2tx+1).
#define HPASS2(SLOT, RR)                                                       \
    do {                                                                       \
        const int jb = 2 * tx + 1;                                             \
        u64 mA = 0ull, qA = 0ull, mB = 0ull, qB = 0ull;                        \
        u64 vP = spab[bs][RR][jb];                                             \
        u64 sP = spq [bs][RR][jb];                                             \
        _Pragma("unroll")                                                      \
        for (int k = 0; k < 11; ++k) {                                         \
            const int kk = (k <= 5) ? k : (11 - k);                            \
            const u64 vC = spab[bs][RR][jb + k + 1];                           \
            const u64 sC = spq [bs][RR][jb + k + 1];                           \
            mA = fma2(vP, WW6[kk], mA);                                        \
            qA = fma2(sP, WW6[kk], qA);                                        \
            mB = fma2(vC, WW6[kk], mB);                                        \
            qB = fma2(sC, WW6[kk], qB);                                        \
            vP = vC; sP = sC;                                                  \
        }                                                                      \
        rm[0][SLOT] = mA; rq[0][SLOT] = qA;                                    \
        rm[1][SLOT] = mB; rq[1][SLOT] = qB;                                    \
    } while (0)

#define VPX(PX, SLOT, RES)                                                     \
    do {                                                                       \
        u64 M = 0ull, Q = 0ull;                                                \
        _Pragma("unroll")                                                      \
        for (int k = 0; k < 11; ++k) {                                         \
            const int s  = ((SLOT) + 1 + k) % 11;                              \
            const int kk = (k <= 5) ? k : (11 - k);                            \
            M = fma2(rm[PX][s], WW6[kk], M);                                   \
            Q = fma2(rq[PX][s], WW6[kk], Q);                                   \
        }                                                                      \
        float mu1, mu2, Ep, Eq;                                                \
        unpack2(M, mu1, mu2); unpack2(Q, Ep, Eq);                              \
        const float mu1sq = mu1 * mu1;                                         \
        const float mu2sq = mu2 * mu2;                                         \
        const float mu12  = mu1 * mu2;                                         \
        const float musq  = mu1sq + mu2sq;                                     \
        const float sig_s = fmaf(0.5f,  Ep + Eq, -musq);                       \
        const float sig12 = fmaf(0.25f, Ep - Eq, -mu12);                       \
        const float num = fmaf(2.f, mu12, C1) * fmaf(2.f, sig12, C2);          \
        const float den = (musq + C1) * (sig_s + C2);                          \
        RES = __fdividef(num, den);                                            \
    } while (0)

#define VPASS2(SLOT, ROW)                                                      \
    do {                                                                       \
        float2 res;                                                            \
        VPX(0, SLOT, res.x);                                                   \
        VPX(1, SLOT, res.y);                                                   \
        *(float2*)(po + (y0 + (ROW) - 2 * HALO) * IMG_W + x0 + 2 * tx) = res;  \
    } while (0)

    for (int ib = 0; ib < NITER; ib += 22) {
#pragma unroll
        for (int jj = 0; jj < 11; ++jj) {
            const int i0 = ib + 2 * jj;
            if (i0 < NITER) {
                PUBLISH(0, R0);
                PUBLISH(1, R1);
                // prefetch next pair (consumed after next sync)
                R0 = load_row(p1, p2, y0 - HALO + i0 + 2, x0, tx);
                R1 = load_row(p1, p2, y0 - HALO + i0 + 3, x0, tx);
                __syncwarp();    // publish -> consume handshake

                const int s0 = (2 * jj) % 11;       // compile-time
                const int s1 = (2 * jj + 1) % 11;   // compile-time
                HPASS2(s0, 0);
                if (i0 >= 2 * HALO) VPASS2(s0, i0);
                HPASS2(s1, 1);
                if (i0 >= 2 * HALO) VPASS2(s1, i0 + 1);
                bs ^= 1;
                // republish of this buffer set is ordered behind the NEXT
                // iteration's __syncwarp -> one sync per iteration suffices
            }
        }
    }
#undef PUBLISH
#undef HPASS2
#undef VPX
#undef VPASS2
}

// ---------------------------------------------------------------------------
extern "C" void kernel_launch(void* const* d_in, const int* in_sizes, int n_in,
                              void* d_out, int out_size) {
    const float* img1 = (const float*)d_in[0];
    const float* img2 = (const float*)d_in[1];
    float* out = (float*)d_out;
    const int n = in_sizes[0];                 // 32*1*512*512 = 8388608

    minmax_kernel<<<MM_BLOCKS, MM_THREADS>>>((const float4*)img1, n / 4);

    dim3 grid(IMG_W / TILE_X, IMG_H / TILE_Y, n / IMG_N);   // (8, 8, 32)
    ssim_kernel<<<grid, NT>>>(img1, img2, out);
}